// round 2
// baseline (speedup 1.0000x reference)
#include <cuda_runtime.h>
#include <cstdint>

// Shapes (fixed by the problem)
#define B  32
#define PL 600
#define T  4096
#define H  256
#define H4 (H / 4)   // 64 float4 per row

// Scratch for the gather index (allocation-free rule: __device__ global)
__device__ int g_idx[B * T];

// ---------------------------------------------------------------------------
// Kernel 1: per-batch inclusive scan of (align[t] != align[t-1]), align[-1]=0
// One block per batch: 256 threads x 16 elements.
// Dtype-agnostic: detects int32 vs int64 storage at runtime (see header note).
// ---------------------------------------------------------------------------
__global__ void idx_kernel(const void* __restrict__ align_raw) {
    const int b   = blockIdx.x;
    const int tid = threadIdx.x;

    // --- dtype detection: int64 (little-endian, values<512) => all odd int32
    // words are zero. int32 sorted-random data essentially never has the
    // first 32 odd words all zero. Reads only the first 64 int32 words,
    // which is in-bounds under either dtype.
    __shared__ int s_is64;
    if (tid == 0) {
        const int* w = (const int*)align_raw;
        int allz = 1;
#pragma unroll
        for (int i = 1; i < 64; i += 2) allz &= (w[i] == 0);
        s_is64 = allz;
    }
    __syncthreads();
    const bool is64 = (s_is64 != 0);

    const long long* a64 = (const long long*)align_raw + (long long)b * T;
    const int*       a32 = (const int*)align_raw + b * T;

    const int base = tid * 16;
    long long prev = 0;
    if (base != 0)
        prev = is64 ? a64[base - 1] : (long long)a32[base - 1];

    int local[16];
    int run = 0;
#pragma unroll
    for (int i = 0; i < 16; ++i) {
        long long v = is64 ? a64[base + i] : (long long)a32[base + i];
        run += (v != prev) ? 1 : 0;
        local[i] = run;           // inclusive within this thread's chunk
        prev = v;
    }

    // Block-wide scan of per-thread totals (Hillis-Steele)
    __shared__ int s[256];
    s[tid] = run;
    __syncthreads();
#pragma unroll
    for (int off = 1; off < 256; off <<= 1) {
        int v = (tid >= off) ? s[tid - off] : 0;
        __syncthreads();
        s[tid] += v;
        __syncthreads();
    }
    const int offset = s[tid] - run;   // exclusive prefix of this thread

    int* out = g_idx + b * T + base;
#pragma unroll
    for (int i = 0; i < 16; ++i) {
        int idx = offset + local[i];
        // clamp for safety (should always hold: #changes <= 512 < PL)
        out[i] = idx < (PL - 1) ? idx : (PL - 1);
    }
}

// ---------------------------------------------------------------------------
// Kernel 2: fused gather + three tiny Linear(1->H) projections.
// One thread per output float4. Grid = B*T*H4 / 256 blocks.
// ---------------------------------------------------------------------------
__global__ void __launch_bounds__(256)
fuse_kernel(const float4* __restrict__ enc,      // [B, PL, H4]
            const float*  __restrict__ pitch,    // [B, T]
            const float*  __restrict__ beats,    // [B, T]
            const float4* __restrict__ w_pitch,  // [H4]
            const float4* __restrict__ b_pitch,
            const float4* __restrict__ w_beats,
            const float4* __restrict__ b_beats,
            const float4* __restrict__ w_pos,
            const float4* __restrict__ b_pos,
            float4*       __restrict__ out)      // [B, T, H4]
{
    const int lin = blockIdx.x * blockDim.x + threadIdx.x;  // < B*T*H4
    const int h4  = lin & (H4 - 1);
    const int bt  = lin >> 6;        // b*T + t
    const int t   = bt & (T - 1);
    const int b   = bt >> 12;

    const int   idx = g_idx[bt];
    const float p   = __ldg(&pitch[bt]);
    const float bt_ = __ldg(&beats[bt]);
    const float pos = (float)t * (1.0f / (float)T);

    const float4 e  = __ldg(&enc[((long long)b * PL + idx) * H4 + h4]);
    const float4 wp = __ldg(&w_pitch[h4]);
    const float4 bp = __ldg(&b_pitch[h4]);
    const float4 wb = __ldg(&w_beats[h4]);
    const float4 bb = __ldg(&b_beats[h4]);
    const float4 wo = __ldg(&w_pos[h4]);
    const float4 bo = __ldg(&b_pos[h4]);

    float4 r;
    r.x = e.x + fmaf(p, wp.x, bp.x) + fmaf(bt_, wb.x, bb.x) + fmaf(pos, wo.x, bo.x);
    r.y = e.y + fmaf(p, wp.y, bp.y) + fmaf(bt_, wb.y, bb.y) + fmaf(pos, wo.y, bo.y);
    r.z = e.z + fmaf(p, wp.z, bp.z) + fmaf(bt_, wb.z, bb.z) + fmaf(pos, wo.z, bo.z);
    r.w = e.w + fmaf(p, wp.w, bp.w) + fmaf(bt_, wb.w, bb.w) + fmaf(pos, wo.w, bo.w);

    out[lin] = r;
}

// ---------------------------------------------------------------------------
// Launch. Inputs (metadata order):
//  0 encoder_out [B,PL,H] f32   1 pitch [B,T] f32   2 beats [B,T] f32
//  3 w_pitch [H] 4 b_pitch [H]  5 w_beats [H] 6 b_beats [H]
//  7 w_pos [H]  8 b_pos [H]     9 align_phone [B,T] int32-or-int64
// ---------------------------------------------------------------------------
extern "C" void kernel_launch(void* const* d_in, const int* in_sizes, int n_in,
                              void* d_out, int out_size) {
    const float4* enc     = (const float4*)d_in[0];
    const float*  pitch   = (const float*)d_in[1];
    const float*  beats   = (const float*)d_in[2];
    const float4* w_pitch = (const float4*)d_in[3];
    const float4* b_pitch = (const float4*)d_in[4];
    const float4* w_beats = (const float4*)d_in[5];
    const float4* b_beats = (const float4*)d_in[6];
    const float4* w_pos   = (const float4*)d_in[7];
    const float4* b_pos   = (const float4*)d_in[8];
    const void*   align   = d_in[9];

    idx_kernel<<<B, 256>>>(align);

    const int total  = B * T * H4;           // 8,388,608 float4
    const int blocks = total / 256;          // 32768
    fuse_kernel<<<blocks, 256>>>(enc, pitch, beats,
                                 w_pitch, b_pitch, w_beats, b_beats,
                                 w_pos, b_pos, (float4*)d_out);
}

// round 3
// speedup vs baseline: 1.5625x; 1.5625x over previous
#include <cuda_runtime.h>
#include <cstdint>

// Shapes (fixed by the problem)
#define B  32
#define PL 600
#define T  4096
#define H  256
#define H4 (H / 4)   // 64 float4 per row

// Scratch: precomputed enc row base offset (in float4 units): (b*PL+idx)*H4
__device__ int g_off[B * T];

// ---------------------------------------------------------------------------
// Kernel 1: per-batch inclusive scan of (align[t] != align[t-1]), align[-1]=0.
// One block per batch: 256 threads x 16 elements. Runtime int32/int64 detect.
// ---------------------------------------------------------------------------
__global__ void idx_kernel(const void* __restrict__ align_raw) {
    const int b   = blockIdx.x;
    const int tid = threadIdx.x;

    // dtype detection: int64 little-endian with values<512 => odd int32 words
    // are all zero; sorted-random int32 data essentially never is.
    __shared__ int s_is64;
    if (tid == 0) {
        const int* w = (const int*)align_raw;
        int allz = 1;
#pragma unroll
        for (int i = 1; i < 64; i += 2) allz &= (w[i] == 0);
        s_is64 = allz;
    }
    __syncthreads();
    const bool is64 = (s_is64 != 0);

    const long long* a64 = (const long long*)align_raw + (long long)b * T;
    const int*       a32 = (const int*)align_raw + b * T;

    const int base = tid * 16;
    long long prev = 0;
    if (base != 0)
        prev = is64 ? a64[base - 1] : (long long)a32[base - 1];

    int local[16];
    int run = 0;
#pragma unroll
    for (int i = 0; i < 16; ++i) {
        long long v = is64 ? a64[base + i] : (long long)a32[base + i];
        run += (v != prev) ? 1 : 0;
        local[i] = run;
        prev = v;
    }

    __shared__ int s[256];
    s[tid] = run;
    __syncthreads();
#pragma unroll
    for (int off = 1; off < 256; off <<= 1) {
        int v = (tid >= off) ? s[tid - off] : 0;
        __syncthreads();
        s[tid] += v;
        __syncthreads();
    }
    const int offset = s[tid] - run;

    int* out = g_off + b * T + base;
    const int rowbase = b * PL;
#pragma unroll
    for (int i = 0; i < 16; ++i) {
        int idx = offset + local[i];
        idx = idx < (PL - 1) ? idx : (PL - 1);       // safety clamp
        out[i] = (rowbase + idx) * H4;               // float4 offset of enc row
    }
}

// ---------------------------------------------------------------------------
// Kernel 2: fused gather + projections, weight-hoisted.
// Block = 256 threads: h4 = tid&63, tl = tid>>6 (4 t-lanes).
// Each thread processes TT=8 consecutive t for its (b, h4).
// Block covers 32 t-values of one batch. Grid = B * T/32 = 4096 blocks.
// ---------------------------------------------------------------------------
#define TT 8

__global__ void __launch_bounds__(256)
fuse_kernel(const float4* __restrict__ enc,      // [B*PL, H4]
            const float*  __restrict__ pitch,    // [B, T]
            const float*  __restrict__ beats,    // [B, T]
            const float4* __restrict__ w_pitch,  // [H4]
            const float4* __restrict__ b_pitch,
            const float4* __restrict__ w_beats,
            const float4* __restrict__ b_beats,
            const float4* __restrict__ w_pos,
            const float4* __restrict__ b_pos,
            float4*       __restrict__ out)      // [B*T, H4]
{
    const int tid = threadIdx.x;
    const int h4  = tid & (H4 - 1);
    const int tl  = tid >> 6;                    // 0..3

    const int b   = blockIdx.x >> 7;             // 128 blocks per batch
    const int t0  = ((blockIdx.x & 127) << 5) + (tl << 3);  // this thread's first t
    const int bt0 = b * T + t0;

    // Hoisted invariants (per thread, once)
    const float4 wp = __ldg(&w_pitch[h4]);
    const float4 wb = __ldg(&w_beats[h4]);
    const float4 wo = __ldg(&w_pos[h4]);
    const float4 bp = __ldg(&b_pitch[h4]);
    const float4 bb = __ldg(&b_beats[h4]);
    const float4 bo = __ldg(&b_pos[h4]);
    float4 bs;
    bs.x = bp.x + bb.x + bo.x;
    bs.y = bp.y + bb.y + bo.y;
    bs.z = bp.z + bb.z + bo.z;
    bs.w = bp.w + bb.w + bo.w;

    float4* o = out + ((long long)bt0 << 6) + h4;

#pragma unroll
    for (int i = 0; i < TT; ++i) {
        const int bt  = bt0 + i;
        const int off = g_off[bt];               // (b*PL+idx)*H4, broadcast
        const float p   = __ldg(&pitch[bt]);
        const float bt_ = __ldg(&beats[bt]);
        const float pos = (float)(t0 + i) * (1.0f / (float)T);

        const float4 e = __ldg(&enc[off + h4]);

        float4 r;
        r.x = e.x + bs.x + p * wp.x + bt_ * wb.x + pos * wo.x;
        r.y = e.y + bs.y + p * wp.y + bt_ * wb.y + pos * wo.y;
        r.z = e.z + bs.z + p * wp.z + bt_ * wb.z + pos * wo.z;
        r.w = e.w + bs.w + p * wp.w + bt_ * wb.w + pos * wo.w;

        o[(long long)i << 6] = r;
    }
}

// ---------------------------------------------------------------------------
// Launch. Inputs (metadata order):
//  0 encoder_out [B,PL,H] f32   1 pitch [B,T] f32   2 beats [B,T] f32
//  3 w_pitch [H] 4 b_pitch [H]  5 w_beats [H] 6 b_beats [H]
//  7 w_pos [H]  8 b_pos [H]     9 align_phone [B,T] int32-or-int64
// ---------------------------------------------------------------------------
extern "C" void kernel_launch(void* const* d_in, const int* in_sizes, int n_in,
                              void* d_out, int out_size) {
    const float4* enc     = (const float4*)d_in[0];
    const float*  pitch   = (const float*)d_in[1];
    const float*  beats   = (const float*)d_in[2];
    const float4* w_pitch = (const float4*)d_in[3];
    const float4* b_pitch = (const float4*)d_in[4];
    const float4* w_beats = (const float4*)d_in[5];
    const float4* b_beats = (const float4*)d_in[6];
    const float4* w_pos   = (const float4*)d_in[7];
    const float4* b_pos   = (const float4*)d_in[8];
    const void*   align   = d_in[9];

    idx_kernel<<<B, 256>>>(align);

    const int blocks = B * (T / 32);             // 4096
    fuse_kernel<<<blocks, 256>>>(enc, pitch, beats,
                                 w_pitch, b_pitch, w_beats, b_beats,
                                 w_pos, b_pos, (float4*)d_out);
}

// round 4
// speedup vs baseline: 2.0089x; 1.2857x over previous
#include <cuda_runtime.h>
#include <cstdint>

// Shapes (fixed by the problem)
#define B  32
#define PL 600
#define T  4096
#define H  256
#define H4 (H / 4)   // 64 float4 per row

// Scratch: precomputed enc row base offset (in float4 units): (b*PL+idx)*H4
__device__ int g_off[B * T];

// ---------------------------------------------------------------------------
// Kernel 1: per-batch inclusive scan of (align[t] != align[t-1]), align[-1]=0.
// One block per batch: 1024 threads x 4 elements, warp-shuffle scan.
// Runtime int32/int64 dtype detection (JAX may emit either).
// ---------------------------------------------------------------------------
__global__ void __launch_bounds__(1024)
idx_kernel(const void* __restrict__ align_raw) {
    const int b    = blockIdx.x;
    const int tid  = threadIdx.x;
    const int lane = tid & 31;
    const int warp = tid >> 5;           // 0..31

    // dtype detection: int64 little-endian with values<512 => odd int32 words
    // are all zero; sorted-random int32 data essentially never is.
    __shared__ int s_is64;
    if (tid == 0) {
        const int* w = (const int*)align_raw;
        int allz = 1;
#pragma unroll
        for (int i = 1; i < 64; i += 2) allz &= (w[i] == 0);
        s_is64 = allz;
    }
    __syncthreads();
    const bool is64 = (s_is64 != 0);

    const long long* a64 = (const long long*)align_raw + (long long)b * T;
    const int*       a32 = (const int*)align_raw + b * T;

    const int base = tid * 4;
    long long prev = 0;
    if (base != 0)
        prev = is64 ? a64[base - 1] : (long long)a32[base - 1];

    int local[4];
    int run = 0;
#pragma unroll
    for (int i = 0; i < 4; ++i) {
        long long v = is64 ? a64[base + i] : (long long)a32[base + i];
        run += (v != prev) ? 1 : 0;
        local[i] = run;
        prev = v;
    }

    // Warp-level inclusive scan of per-thread totals
    int incl = run;
#pragma unroll
    for (int off = 1; off < 32; off <<= 1) {
        int v = __shfl_up_sync(0xffffffffu, incl, off);
        if (lane >= off) incl += v;
    }

    __shared__ int wsum[32];
    if (lane == 31) wsum[warp] = incl;
    __syncthreads();

    if (warp == 0) {
        int v = wsum[lane];
#pragma unroll
        for (int off = 1; off < 32; off <<= 1) {
            int u = __shfl_up_sync(0xffffffffu, v, off);
            if (lane >= off) v += u;
        }
        wsum[lane] = v;                  // inclusive warp totals
    }
    __syncthreads();

    const int warp_off = (warp == 0) ? 0 : wsum[warp - 1];
    const int offset   = warp_off + incl - run;   // exclusive prefix of thread

    int* out = g_off + b * T + base;
    const int rowbase = b * PL;
#pragma unroll
    for (int i = 0; i < 4; ++i) {
        int idx = offset + local[i];
        idx = idx < (PL - 1) ? idx : (PL - 1);    // safety clamp
        out[i] = (rowbase + idx) * H4;            // float4 offset of enc row
    }
}

// ---------------------------------------------------------------------------
// Kernel 2: fused gather + projections, weight-hoisted.
// Block = 256 threads: h4 = tid&63, tl = tid>>6 (4 t-lanes).
// Each thread processes TT=8 consecutive t for its (b, h4).
// Block covers 32 t-values of one batch. Grid = B * T/32 = 4096 blocks.
// ---------------------------------------------------------------------------
#define TT 8

__global__ void __launch_bounds__(256)
fuse_kernel(const float4* __restrict__ enc,      // [B*PL, H4]
            const float*  __restrict__ pitch,    // [B, T]
            const float*  __restrict__ beats,    // [B, T]
            const float4* __restrict__ w_pitch,  // [H4]
            const float4* __restrict__ b_pitch,
            const float4* __restrict__ w_beats,
            const float4* __restrict__ b_beats,
            const float4* __restrict__ w_pos,
            const float4* __restrict__ b_pos,
            float4*       __restrict__ out)      // [B*T, H4]
{
    const int tid = threadIdx.x;
    const int h4  = tid & (H4 - 1);
    const int tl  = tid >> 6;                    // 0..3

    const int b   = blockIdx.x >> 7;             // 128 blocks per batch
    const int t0  = ((blockIdx.x & 127) << 5) + (tl << 3);
    const int bt0 = b * T + t0;

    // Hoisted invariants (per thread, once)
    const float4 wp = __ldg(&w_pitch[h4]);
    const float4 wb = __ldg(&w_beats[h4]);
    const float4 wo = __ldg(&w_pos[h4]);
    const float4 bp = __ldg(&b_pitch[h4]);
    const float4 bb = __ldg(&b_beats[h4]);
    const float4 bo = __ldg(&b_pos[h4]);
    float4 bs;
    bs.x = bp.x + bb.x + bo.x;
    bs.y = bp.y + bb.y + bo.y;
    bs.z = bp.z + bb.z + bo.z;
    bs.w = bp.w + bb.w + bo.w;

    // Phase A: issue all broadcast scalar loads up front (independent)
    int   off[TT];
    float p[TT], bv[TT];
#pragma unroll
    for (int i = 0; i < TT; ++i) {
        off[i] = g_off[bt0 + i];
        p[i]   = __ldg(&pitch[bt0 + i]);
        bv[i]  = __ldg(&beats[bt0 + i]);
    }

    float4* o = out + ((long long)bt0 << 6) + h4;

    // Phase B: enc gather + fused projections + streaming store
#pragma unroll
    for (int i = 0; i < TT; ++i) {
        const float pos = (float)(t0 + i) * (1.0f / (float)T);
        const float4 e  = __ldg(&enc[off[i] + h4]);

        float4 r;
        r.x = e.x + bs.x + p[i] * wp.x + bv[i] * wb.x + pos * wo.x;
        r.y = e.y + bs.y + p[i] * wp.y + bv[i] * wb.y + pos * wo.y;
        r.z = e.z + bs.z + p[i] * wp.z + bv[i] * wb.z + pos * wo.z;
        r.w = e.w + bs.w + p[i] * wp.w + bv[i] * wb.w + pos * wo.w;

        __stcs(o + ((long long)i << 6), r);      // write-once: evict-first
    }
}

// ---------------------------------------------------------------------------
// Launch. Inputs (metadata order):
//  0 encoder_out [B,PL,H] f32   1 pitch [B,T] f32   2 beats [B,T] f32
//  3 w_pitch [H] 4 b_pitch [H]  5 w_beats [H] 6 b_beats [H]
//  7 w_pos [H]  8 b_pos [H]     9 align_phone [B,T] int32-or-int64
// ---------------------------------------------------------------------------
extern "C" void kernel_launch(void* const* d_in, const int* in_sizes, int n_in,
                              void* d_out, int out_size) {
    const float4* enc     = (const float4*)d_in[0];
    const float*  pitch   = (const float*)d_in[1];
    const float*  beats   = (const float*)d_in[2];
    const float4* w_pitch = (const float4*)d_in[3];
    const float4* b_pitch = (const float4*)d_in[4];
    const float4* w_beats = (const float4*)d_in[5];
    const float4* b_beats = (const float4*)d_in[6];
    const float4* w_pos   = (const float4*)d_in[7];
    const float4* b_pos   = (const float4*)d_in[8];
    const void*   align   = d_in[9];

    idx_kernel<<<B, 1024>>>(align);

    const int blocks = B * (T / 32);             // 4096
    fuse_kernel<<<blocks, 256>>>(enc, pitch, beats,
                                 w_pitch, b_pitch, w_beats, b_beats,
                                 w_pos, b_pos, (float4*)d_out);
}